// round 11
// baseline (speedup 1.0000x reference)
#include <cuda_runtime.h>
#include <cstdint>
#include <cstddef>

// Problem constants
#define BB 32
#define TT 2048
#define DD 256
#define HH 512
#define G4 2048           // 4*H
#define KTOT 768          // H + D

#define NCTA 128
#define NTHR 256

// ---- shared memory layout (float offsets) ----
#define OFF_WS  0                          // Ws[768][16]        48 KB
#define OFF_HX  (KTOT * 16)                // hx[768][36]        108 KB (rows 0..511 h, 512..767 x)
#define OFF_RED (OFF_HX + KTOT * 36)       // red: 16*258 float2 33 KB
#define OFF_GB  (OFF_RED + 16 * 258 * 2)   // gbuf: 256 float2
#define OFF_BS  (OFF_GB + 512)             // bias[16]
#define OFF_CST (OFF_BS + 16)              // c state [b*4+u]
#define OFF_LC  (OFF_CST + 128)            // latched c
#define OFF_LH  (OFF_LC + 128)             // latched h
#define OFF_LEN (OFF_LH + 128)             // datalens[32] (int)
#define SMEM_FLOATS (OFF_LEN + 32)
#define SMEM_BYTES  (SMEM_FLOATS * 4)      // ~197 KB

// Persistent cross-CTA state (zero-initialized at module load)
__device__ __align__(16) float g_hT[2][HH * BB];  // double-buffered h, layout [k][b]
__device__ unsigned int g_cnt;                     // barrier arrivals (self-resetting)
__device__ unsigned int g_epoch;                   // monotone epoch across replays

// ---- packed f32x2 helpers (sm_103a) ----
__device__ __forceinline__ unsigned long long dup2(float f) {
    unsigned long long r;
    asm("mov.b64 %0, {%1, %1};" : "=l"(r) : "r"(__float_as_uint(f)));
    return r;
}
#define FMA2(acc, h2, w2) \
    asm("fma.rn.f32x2 %0, %1, %2, %0;" : "+l"(acc) : "l"(h2), "l"(w2))

__device__ __forceinline__ float sigf(float x) {
    return 1.0f / (1.0f + expf(-x));
}

// One K-step: 4 batch-pairs (8 batches) x 4 cols, all operands in SMEM.
#define K_STEP(WP, HP)                                                        \
    {                                                                         \
        ulonglong2 hA = *(const ulonglong2*)(HP);                             \
        ulonglong2 hB = *(const ulonglong2*)((HP) + 4);                       \
        float4 wv = *(const float4*)(WP);                                     \
        unsigned long long w0 = dup2(wv.x), w1 = dup2(wv.y),                  \
                           w2 = dup2(wv.z), w3 = dup2(wv.w);                  \
        FMA2(a00, hA.x, w0); FMA2(a01, hA.x, w1);                             \
        FMA2(a02, hA.x, w2); FMA2(a03, hA.x, w3);                             \
        FMA2(a10, hA.y, w0); FMA2(a11, hA.y, w1);                             \
        FMA2(a12, hA.y, w2); FMA2(a13, hA.y, w3);                             \
        FMA2(a20, hB.x, w0); FMA2(a21, hB.x, w1);                             \
        FMA2(a22, hB.x, w2); FMA2(a23, hB.x, w3);                             \
        FMA2(a30, hB.y, w0); FMA2(a31, hB.y, w1);                             \
        FMA2(a32, hB.y, w2); FMA2(a33, hB.y, w3);                             \
    }

__global__ void __launch_bounds__(NTHR, 1)
k_lstm(const float* __restrict__ X,     // [B][T][D]
       const int*   __restrict__ lens,  // [B]
       const float* __restrict__ Wi,    // [D][4H]
       const float* __restrict__ Wh,    // [H][4H]
       const float* __restrict__ bias,  // [4H]
       float* __restrict__ out)         // lc[B,H] | lh[B,H] | ys[B,T,H]
{
    extern __shared__ float sm[];
    float*  Ws   = sm + OFF_WS;             // [768][16]
    float*  hx   = sm + OFF_HX;             // [768][36]: h rows then x rows
    float2* red  = (float2*)(sm + OFF_RED); // [16][258]
    float2* gbuf = (float2*)(sm + OFF_GB);  // [256]
    float*  bs   = sm + OFF_BS;
    float*  cst  = sm + OFF_CST;
    float*  lcs  = sm + OFF_LC;
    float*  lhs  = sm + OFF_LH;
    int*    slen = (int*)(sm + OFF_LEN);

    const int tid = threadIdx.x;
    const int hc  = blockIdx.x * 4;         // this CTA's 4 h-units

    // ---- one-time setup ----
    // Weight slice: Ws[k][q*4+c] = W[k][q*512 + hc + c], k<512 from Wh else Wi.
    for (int i = tid; i < KTOT * 4; i += NTHR) {
        int k = i >> 2, q = i & 3;
        const float* src = (k < HH) ? (Wh + (size_t)k * G4)
                                    : (Wi + (size_t)(k - HH) * G4);
        *(float4*)&Ws[k * 16 + q * 4] = *(const float4*)&src[q * HH + hc];
    }
    if (tid < 16) bs[tid] = bias[(tid >> 2) * HH + hc + (tid & 3)];
    if (tid < BB) slen[tid] = lens[tid];
    if (tid < 128) { cst[tid] = 0.0f; lcs[tid] = 0.0f; lhs[tid] = 0.0f; }

    unsigned int base = 0;
    if (tid == 0) base = *(volatile unsigned int*)&g_epoch;  // pre-arrival snapshot
    __syncthreads();

    // GEMM thread decomposition: 16 output tiles x 16-way K-split
    const int og = tid & 15;
    const int kg = tid >> 4;          // 0..15
    const int bg = og >> 2;           // batch-pair group (8 batches)
    const int cg = og & 3;            // col group (4 cols)

    for (int s = 0; s < TT; s++) {
        // ---- stage x_t transposed into hx rows [512..768): hx[(512+d)*36 + b] ----
        for (int i = tid; i < (BB * DD) / 4; i += NTHR) {
            int b = i >> 6, d4 = (i & 63) << 2;
            float4 v = *(const float4*)&X[((size_t)b * TT + s) * DD + d4];
            float* dst = &hx[(HH + d4) * 36 + b];
            dst[0] = v.x; dst[36] = v.y; dst[72] = v.z; dst[108] = v.w;
        }
        __syncthreads();

        unsigned long long a00=0,a01=0,a02=0,a03=0, a10=0,a11=0,a12=0,a13=0,
                           a20=0,a21=0,a22=0,a23=0, a30=0,a31=0,a32=0,a33=0;

        // ---- x partial GEMM (h-independent: hides the barrier wait) ----
        {
            const float* wp = Ws + (HH + kg * 16) * 16 + cg * 4;
            const float* hp = hx + (HH + kg * 16) * 36 + bg * 8;
#pragma unroll
            for (int kk = 0; kk < 16; kk++) { K_STEP(wp, hp); wp += 16; hp += 36; }
        }

        if (s > 0) {
            // ---- grid barrier: wait until all CTAs published h(s-1) ----
            if (tid == 0) {
                unsigned int target = base + (unsigned int)s;
                while ((int)(*(volatile unsigned int*)&g_epoch - target) < 0)
                    __nanosleep(40);
                __threadfence();
            }
            __syncthreads();

            // ---- stage h(s-1) from g_hT[s&1] into hx rows [0..512) ----
            {
                const float* src = g_hT[s & 1];
                for (int i = tid; i < (HH * BB) / 4; i += NTHR) {
                    int k = i >> 3, b4 = (i & 7) << 2;
                    float4 v = *(const float4*)&src[k * BB + b4];
                    *(float4*)&hx[k * 36 + b4] = v;
                }
            }
            __syncthreads();

            // ---- h GEMM (32 K-steps per thread) ----
            {
                const float* wp = Ws + (kg * 32) * 16 + cg * 4;
                const float* hp = hx + (kg * 32) * 36 + bg * 8;
#pragma unroll 8
                for (int kk = 0; kk < 32; kk++) { K_STEP(wp, hp); wp += 16; hp += 36; }
            }
        }
        __syncthreads();

        // ---- K-split reduction: red[kg][pair*16 + col] ----
        {
            int base2 = kg * 258 + (bg * 4) * 16 + cg * 4;   // even -> 16B aligned
            *(ulonglong2*)&red[base2         ] = make_ulonglong2(a00, a01);
            *(ulonglong2*)&red[base2      + 2] = make_ulonglong2(a02, a03);
            *(ulonglong2*)&red[base2 + 16    ] = make_ulonglong2(a10, a11);
            *(ulonglong2*)&red[base2 + 16 + 2] = make_ulonglong2(a12, a13);
            *(ulonglong2*)&red[base2 + 32    ] = make_ulonglong2(a20, a21);
            *(ulonglong2*)&red[base2 + 32 + 2] = make_ulonglong2(a22, a23);
            *(ulonglong2*)&red[base2 + 48    ] = make_ulonglong2(a30, a31);
            *(ulonglong2*)&red[base2 + 48 + 2] = make_ulonglong2(a32, a33);
        }
        __syncthreads();
        {
            float2 acc = make_float2(0.0f, 0.0f);
#pragma unroll
            for (int g = 0; g < 16; g++) {
                float2 v = red[g * 258 + tid];
                acc.x += v.x; acc.y += v.y;
            }
            gbuf[tid] = acc;   // slot = batchPair*16 + gate*4 + unit
        }
        __syncthreads();

        // ---- gates / state update / publish: one (batch, unit) per thread ----
        if (tid < 128) {
            int b  = tid >> 2, u = tid & 3;
            int bp = b >> 1, hi = b & 1;
            float2 vi = gbuf[bp * 16 +      u];
            float2 vf = gbuf[bp * 16 +  4 + u];
            float2 vg = gbuf[bp * 16 +  8 + u];
            float2 vo = gbuf[bp * 16 + 12 + u];
            float gi = (hi ? vi.y : vi.x) + bs[     u];
            float gf = (hi ? vf.y : vf.x) + bs[ 4 + u];
            float gg = (hi ? vg.y : vg.x) + bs[ 8 + u];
            float go = (hi ? vo.y : vo.x) + bs[12 + u];

            float c_old = cst[tid];
            float cn = sigf(gf) * c_old + sigf(gi) * tanhf(gg);
            float hn = sigf(go) * tanhf(cn);
            cst[tid] = cn;

            // publish h(s) to the buffer step s+1 will read: g_hT[(s+1)&1]
            g_hT[(s + 1) & 1][(hc + u) * BB + b] = hn;

            // ys output (unmasked, every step)
            out[2 * BB * HH + ((size_t)b * TT + s) * HH + hc + u] = hn;

            if (s < slen[b]) { lcs[tid] = cn; lhs[tid] = hn; }
            __threadfence();   // make this thread's g_hT write device-visible
        }
        __syncthreads();

        // ---- arrive: last CTA resets counter and bumps epoch ----
        if (tid == 0) {
            unsigned int old = atomicAdd(&g_cnt, 1u);
            if (old == NCTA - 1) {
                atomicExch(&g_cnt, 0u);
                __threadfence();
                atomicAdd(&g_epoch, 1u);
            }
        }
        // no sync needed here: next iteration's staging only touches private smem
        // regions already quiesced by the __syncthreads above.
    }

    // ---- final latched carry ----
    if (tid < 128) {
        int b = tid >> 2, u = tid & 3;
        out[          (size_t)b * HH + hc + u] = lcs[tid];   // lc
        out[BB * HH + (size_t)b * HH + hc + u] = lhs[tid];   // lh
    }
}

extern "C" void kernel_launch(void* const* d_in, const int* in_sizes, int n_in,
                              void* d_out, int out_size) {
    const float* X    = (const float*)d_in[0];   // datamat [B,T,D]
    const int*   lens = (const int*)  d_in[1];   // datalens [B]
    const float* Wi   = (const float*)d_in[2];   // [D,4H]
    const float* Wh   = (const float*)d_in[3];   // [H,4H]
    const float* bias = (const float*)d_in[4];   // [4H]
    float* out = (float*)d_out;

    cudaFuncSetAttribute(k_lstm, cudaFuncAttributeMaxDynamicSharedMemorySize,
                         SMEM_BYTES);

    k_lstm<<<NCTA, NTHR, SMEM_BYTES>>>(X, lens, Wi, Wh, bias, out);
}

// round 12
// speedup vs baseline: 1.0488x; 1.0488x over previous
#include <cuda_runtime.h>
#include <cstdint>
#include <cstddef>

// Problem constants
#define BB 32
#define TT 2048
#define DD 256
#define HH 512
#define G4 2048           // 4*H
#define KTOT 768          // H + D

#define NCTA 128
#define NTHR 512

// ---- shared memory layout (float offsets) ----
#define OFF_WS  0                          // Ws[768][16]            48 KB
#define OFF_HX  (KTOT * 16)                // hx[768][36]            108 KB (h rows 0..511, x rows 512..767)
                                           // red[32][258] float2 ALIASES hx (dead after GEMMs)
#define OFF_GB  (OFF_HX + KTOT * 36)       // gbuf: 256 float2
#define OFF_BS  (OFF_GB + 512)             // bias[16]
#define OFF_CST (OFF_BS + 16)              // c state [b*4+u]
#define OFF_LC  (OFF_CST + 128)            // latched c
#define OFF_LH  (OFF_LC + 128)             // latched h
#define OFF_LEN (OFF_LH + 128)             // datalens[32] (int)
#define SMEM_FLOATS (OFF_LEN + 32)
#define SMEM_BYTES  (SMEM_FLOATS * 4)      // ~164 KB

// Persistent cross-CTA state (zero-initialized at module load)
__device__ __align__(16) float g_hT[2][HH * BB];  // double-buffered h, layout [k][b]
__device__ unsigned int g_cnt;                     // barrier arrivals (self-resetting)
__device__ unsigned int g_epoch;                   // monotone epoch across replays

// ---- packed f32x2 helpers (sm_103a) ----
__device__ __forceinline__ unsigned long long dup2(float f) {
    unsigned long long r;
    asm("mov.b64 %0, {%1, %1};" : "=l"(r) : "r"(__float_as_uint(f)));
    return r;
}
#define FMA2(acc, h2, w2) \
    asm("fma.rn.f32x2 %0, %1, %2, %0;" : "+l"(acc) : "l"(h2), "l"(w2))

__device__ __forceinline__ float sigf(float x) {
    return __fdividef(1.0f, 1.0f + __expf(-x));
}
__device__ __forceinline__ float tanhfast(float x) {
    // tanh(x) = 1 - 2/(exp(2x)+1); numerically fine for gate range, |err|~1e-6
    return 1.0f - __fdividef(2.0f, __expf(2.0f * x) + 1.0f);
}

// One K-step: 4 batch-pairs (8 batches) x 4 cols, all operands in SMEM.
#define K_STEP(WP, HP)                                                        \
    {                                                                         \
        ulonglong2 hA = *(const ulonglong2*)(HP);                             \
        ulonglong2 hB = *(const ulonglong2*)((HP) + 4);                       \
        float4 wv = *(const float4*)(WP);                                     \
        unsigned long long w0 = dup2(wv.x), w1 = dup2(wv.y),                  \
                           w2 = dup2(wv.z), w3 = dup2(wv.w);                  \
        FMA2(a00, hA.x, w0); FMA2(a01, hA.x, w1);                             \
        FMA2(a02, hA.x, w2); FMA2(a03, hA.x, w3);                             \
        FMA2(a10, hA.y, w0); FMA2(a11, hA.y, w1);                             \
        FMA2(a12, hA.y, w2); FMA2(a13, hA.y, w3);                             \
        FMA2(a20, hB.x, w0); FMA2(a21, hB.x, w1);                             \
        FMA2(a22, hB.x, w2); FMA2(a23, hB.x, w3);                             \
        FMA2(a30, hB.y, w0); FMA2(a31, hB.y, w1);                             \
        FMA2(a32, hB.y, w2); FMA2(a33, hB.y, w3);                             \
    }

__global__ void __launch_bounds__(NTHR, 1)
k_lstm(const float* __restrict__ X,     // [B][T][D]
       const int*   __restrict__ lens,  // [B]
       const float* __restrict__ Wi,    // [D][4H]
       const float* __restrict__ Wh,    // [H][4H]
       const float* __restrict__ bias,  // [4H]
       float* __restrict__ out)         // lc[B,H] | lh[B,H] | ys[B,T,H]
{
    extern __shared__ float sm[];
    float*  Ws   = sm + OFF_WS;             // [768][16]
    float*  hx   = sm + OFF_HX;             // [768][36]
    float2* red  = (float2*)(sm + OFF_HX);  // [32][258], aliases hx
    float2* gbuf = (float2*)(sm + OFF_GB);  // [256]
    float*  bs   = sm + OFF_BS;
    float*  cst  = sm + OFF_CST;
    float*  lcs  = sm + OFF_LC;
    float*  lhs  = sm + OFF_LH;
    int*    slen = (int*)(sm + OFF_LEN);

    const int tid = threadIdx.x;
    const int hc  = blockIdx.x * 4;         // this CTA's 4 h-units

    // ---- one-time setup ----
    for (int i = tid; i < KTOT * 4; i += NTHR) {
        int k = i >> 2, q = i & 3;
        const float* src = (k < HH) ? (Wh + (size_t)k * G4)
                                    : (Wi + (size_t)(k - HH) * G4);
        *(float4*)&Ws[k * 16 + q * 4] = *(const float4*)&src[q * HH + hc];
    }
    if (tid < 16) bs[tid] = bias[(tid >> 2) * HH + hc + (tid & 3)];
    if (tid < BB) slen[tid] = lens[tid];
    if (tid < 128) { cst[tid] = 0.0f; lcs[tid] = 0.0f; lhs[tid] = 0.0f; }

    unsigned int base = 0;
    if (tid == 0) base = *(volatile unsigned int*)&g_epoch;  // pre-arrival snapshot
    __syncthreads();

    // GEMM decomposition: 16 output tiles x 32-way K-split
    const int og = tid & 15;
    const int kg = tid >> 4;          // 0..31
    const int bg = og >> 2;           // batch-pair group (8 batches)
    const int cg = og & 3;            // col group (4 cols)

    for (int s = 0; s < TT; s++) {
        // ---- stage x_t transposed into hx rows [512..768) ----
        for (int i = tid; i < (BB * DD) / 4; i += NTHR) {
            int b = i >> 6, d4 = (i & 63) << 2;
            float4 v = __ldcg((const float4*)&X[((size_t)b * TT + s) * DD + d4]);
            float* dst = &hx[(HH + d4) * 36 + b];
            dst[0] = v.x; dst[36] = v.y; dst[72] = v.z; dst[108] = v.w;
        }
        __syncthreads();

        unsigned long long a00=0,a01=0,a02=0,a03=0, a10=0,a11=0,a12=0,a13=0,
                           a20=0,a21=0,a22=0,a23=0, a30=0,a31=0,a32=0,a33=0;

        // ---- x partial GEMM (h-independent: hides the barrier wait) ----
        {
            const float* wp = Ws + (HH + kg * 8) * 16 + cg * 4;
            const float* hp = hx + (HH + kg * 8) * 36 + bg * 8;
#pragma unroll
            for (int kk = 0; kk < 8; kk++) { K_STEP(wp, hp); wp += 16; hp += 36; }
        }

        if (s > 0) {
            // ---- grid barrier: wait for h(s-1) ----
            if (tid == 0) {
                unsigned int target = base + (unsigned int)s;
                while ((int)(*(volatile unsigned int*)&g_epoch - target) < 0)
                    __nanosleep(32);
                __threadfence();   // acquire + L1 invalidate, once per step
            }
            __syncthreads();

            // ---- stage h(s-1) (L2-direct) into hx rows [0..512) ----
            {
                const float* src = g_hT[s & 1];
                for (int i = tid; i < (HH * BB) / 4; i += NTHR) {
                    int k = i >> 3, b4 = (i & 7) << 2;
                    float4 v = __ldcg((const float4*)&src[k * BB + b4]);
                    *(float4*)&hx[k * 36 + b4] = v;
                }
            }
            __syncthreads();

            // ---- h GEMM (16 K-steps per thread) ----
            {
                const float* wp = Ws + (kg * 16) * 16 + cg * 4;
                const float* hp = hx + (kg * 16) * 36 + bg * 8;
#pragma unroll
                for (int kk = 0; kk < 16; kk++) { K_STEP(wp, hp); wp += 16; hp += 36; }
            }
        }
        __syncthreads();   // hx reads done before red (aliased) overwrites it

        // ---- K-split reduction: red[kg][pair*16 + col] ----
        {
            int base2 = kg * 258 + (bg * 4) * 16 + cg * 4;   // even -> 16B aligned
            *(ulonglong2*)&red[base2         ] = make_ulonglong2(a00, a01);
            *(ulonglong2*)&red[base2      + 2] = make_ulonglong2(a02, a03);
            *(ulonglong2*)&red[base2 + 16    ] = make_ulonglong2(a10, a11);
            *(ulonglong2*)&red[base2 + 16 + 2] = make_ulonglong2(a12, a13);
            *(ulonglong2*)&red[base2 + 32    ] = make_ulonglong2(a20, a21);
            *(ulonglong2*)&red[base2 + 32 + 2] = make_ulonglong2(a22, a23);
            *(ulonglong2*)&red[base2 + 48    ] = make_ulonglong2(a30, a31);
            *(ulonglong2*)&red[base2 + 48 + 2] = make_ulonglong2(a32, a33);
        }
        __syncthreads();
        if (tid < 256) {
            float2 acc = make_float2(0.0f, 0.0f);
#pragma unroll
            for (int g = 0; g < 32; g++) {
                float2 v = red[g * 258 + tid];
                acc.x += v.x; acc.y += v.y;
            }
            gbuf[tid] = acc;   // slot = batchPair*16 + gate*4 + unit
        }
        __syncthreads();

        // ---- gates / state update / publish ----
        if (tid < 128) {
            int b  = tid >> 2, u = tid & 3;
            int bp = b >> 1, hi = b & 1;
            float2 vi = gbuf[bp * 16 +      u];
            float2 vf = gbuf[bp * 16 +  4 + u];
            float2 vg = gbuf[bp * 16 +  8 + u];
            float2 vo = gbuf[bp * 16 + 12 + u];
            float gi = (hi ? vi.y : vi.x) + bs[     u];
            float gf = (hi ? vf.y : vf.x) + bs[ 4 + u];
            float gg = (hi ? vg.y : vg.x) + bs[ 8 + u];
            float go = (hi ? vo.y : vo.x) + bs[12 + u];

            float c_old = cst[tid];
            float cn = sigf(gf) * c_old + sigf(gi) * tanhfast(gg);
            float hn = sigf(go) * tanhfast(cn);
            cst[tid] = cn;

            // publish h(s) to the buffer step s+1 reads
            g_hT[(s + 1) & 1][(hc + u) * BB + b] = hn;

            // ys output (unmasked, every step)
            out[2 * BB * HH + ((size_t)b * TT + s) * HH + hc + u] = hn;

            if (s < slen[b]) { lcs[tid] = cn; lhs[tid] = hn; }
        }
        __syncthreads();   // all publishes visible to tid0 before the fence

        // ---- arrive: single cumulative fence, last CTA bumps epoch ----
        if (tid == 0) {
            __threadfence();                       // release peers' g_hT writes
            unsigned int old = atomicAdd(&g_cnt, 1u);
            if (old == NCTA - 1) {
                atomicExch(&g_cnt, 0u);
                __threadfence();
                atomicAdd(&g_epoch, 1u);
            }
        }
        // next iteration's x staging only touches smem quiesced by the bar above
    }

    // ---- final latched carry ----
    if (tid < 128) {
        int b = tid >> 2, u = tid & 3;
        out[          (size_t)b * HH + hc + u] = lcs[tid];   // lc
        out[BB * HH + (size_t)b * HH + hc + u] = lhs[tid];   // lh
    }
}

extern "C" void kernel_launch(void* const* d_in, const int* in_sizes, int n_in,
                              void* d_out, int out_size) {
    const float* X    = (const float*)d_in[0];   // datamat [B,T,D]
    const int*   lens = (const int*)  d_in[1];   // datalens [B]
    const float* Wi   = (const float*)d_in[2];   // [D,4H]
    const float* Wh   = (const float*)d_in[3];   // [H,4H]
    const float* bias = (const float*)d_in[4];   // [4H]
    float* out = (float*)d_out;

    cudaFuncSetAttribute(k_lstm, cudaFuncAttributeMaxDynamicSharedMemorySize,
                         SMEM_BYTES);

    k_lstm<<<NCTA, NTHR, SMEM_BYTES>>>(X, lens, Wi, Wh, bias, out);
}

// round 13
// speedup vs baseline: 1.1805x; 1.1255x over previous
#include <cuda_runtime.h>
#include <cstdint>
#include <cstddef>

// Problem constants
#define BB 32
#define TT 2048
#define DD 256
#define HH 512
#define G4 2048           // 4*H
#define KTOT 768          // H + D

#define NCTA 128
#define NTHR 512

// ---- shared memory layout (float offsets) ----
#define OFF_WS  0                          // Ws[768][16]            48 KB
#define OFF_HX  (KTOT * 16)                // hx[768][36]            108 KB (h rows 0..511, x rows 512..767)
                                           // red[32][258] float2 ALIASES hx h-rows (dead after GEMMs)
#define OFF_GB  (OFF_HX + KTOT * 36)       // gb2: 2*256 float2 = 1024 floats
#define OFF_BS  (OFF_GB + 1024)            // bias[16]
#define OFF_CST (OFF_BS + 16)              // c state [b*4+u]
#define OFF_LC  (OFF_CST + 128)            // latched c
#define OFF_LH  (OFF_LC + 128)             // latched h
#define OFF_LEN (OFF_LH + 128)             // datalens[32] (int)
#define SMEM_FLOATS (OFF_LEN + 32)
#define SMEM_BYTES  (SMEM_FLOATS * 4)      // ~162 KB

// Persistent cross-CTA state (zero-initialized at module load)
__device__ __align__(16) float g_hT[2][HH * BB];  // double-buffered h, layout [k][b]
__device__ unsigned int g_cnt;                     // monotone arrival counter (never reset)

// ---- packed f32x2 helpers (sm_103a) ----
__device__ __forceinline__ unsigned long long dup2(float f) {
    unsigned long long r;
    asm("mov.b64 %0, {%1, %1};" : "=l"(r) : "r"(__float_as_uint(f)));
    return r;
}
#define FMA2(acc, h2, w2) \
    asm("fma.rn.f32x2 %0, %1, %2, %0;" : "+l"(acc) : "l"(h2), "l"(w2))

__device__ __forceinline__ unsigned int ldacq(const unsigned int* p) {
    unsigned int v;
    asm volatile("ld.acquire.gpu.global.u32 %0, [%1];" : "=r"(v) : "l"(p));
    return v;
}
__device__ __forceinline__ void red_release_add(unsigned int* p, unsigned int v) {
    asm volatile("red.release.gpu.global.add.u32 [%0], %1;" :: "l"(p), "r"(v) : "memory");
}

__device__ __forceinline__ float sigf(float x) {
    return __fdividef(1.0f, 1.0f + __expf(-x));
}
__device__ __forceinline__ float tanhfast(float x) {
    return 1.0f - __fdividef(2.0f, __expf(2.0f * x) + 1.0f);
}

// One K-step: 4 batch-pairs (8 batches) x 4 cols, all operands in SMEM.
#define K_STEP(WP, HP)                                                        \
    {                                                                         \
        ulonglong2 hA = *(const ulonglong2*)(HP);                             \
        ulonglong2 hB = *(const ulonglong2*)((HP) + 4);                       \
        float4 wv = *(const float4*)(WP);                                     \
        unsigned long long w0 = dup2(wv.x), w1 = dup2(wv.y),                  \
                           w2 = dup2(wv.z), w3 = dup2(wv.w);                  \
        FMA2(a00, hA.x, w0); FMA2(a01, hA.x, w1);                             \
        FMA2(a02, hA.x, w2); FMA2(a03, hA.x, w3);                             \
        FMA2(a10, hA.y, w0); FMA2(a11, hA.y, w1);                             \
        FMA2(a12, hA.y, w2); FMA2(a13, hA.y, w3);                             \
        FMA2(a20, hB.x, w0); FMA2(a21, hB.x, w1);                             \
        FMA2(a22, hB.x, w2); FMA2(a23, hB.x, w3);                             \
        FMA2(a30, hB.y, w0); FMA2(a31, hB.y, w1);                             \
        FMA2(a32, hB.y, w2); FMA2(a33, hB.y, w3);                             \
    }

__global__ void __launch_bounds__(NTHR, 1)
k_lstm(const float* __restrict__ X,     // [B][T][D]
       const int*   __restrict__ lens,  // [B]
       const float* __restrict__ Wi,    // [D][4H]
       const float* __restrict__ Wh,    // [H][4H]
       const float* __restrict__ bias,  // [4H]
       float* __restrict__ out)         // lc[B,H] | lh[B,H] | ys[B,T,H]
{
    extern __shared__ float sm[];
    float*  Ws   = sm + OFF_WS;             // [768][16]
    float*  hx   = sm + OFF_HX;             // [768][36]
    float2* red  = (float2*)(sm + OFF_HX);  // [32][258], aliases hx h-rows
    float2* gb2  = (float2*)(sm + OFF_GB);  // [2][256]
    float*  bs   = sm + OFF_BS;
    float*  cst  = sm + OFF_CST;
    float*  lcs  = sm + OFF_LC;
    float*  lhs  = sm + OFF_LH;
    int*    slen = (int*)(sm + OFF_LEN);

    const int tid = threadIdx.x;
    const int hc  = blockIdx.x * 4;         // this CTA's 4 h-units

    // ---- one-time setup ----
    for (int i = tid; i < KTOT * 4; i += NTHR) {
        int k = i >> 2, q = i & 3;
        const float* src = (k < HH) ? (Wh + (size_t)k * G4)
                                    : (Wi + (size_t)(k - HH) * G4);
        *(float4*)&Ws[k * 16 + q * 4] = *(const float4*)&src[q * HH + hc];
    }
    if (tid < 16) bs[tid] = bias[(tid >> 2) * HH + hc + (tid & 3)];
    if (tid < BB) slen[tid] = lens[tid];
    if (tid < 128) { cst[tid] = 0.0f; lcs[tid] = 0.0f; lhs[tid] = 0.0f; }

    // per-run arrival baseline (read long before any CTA's first arrival)
    unsigned int base = 0;
    if (tid == 0) base = *(volatile unsigned int*)&g_cnt;
    __syncthreads();

    // GEMM decomposition: 16 output tiles x 32-way K-split
    const int og = tid & 15;
    const int kg = tid >> 4;          // 0..31
    const int bg = og >> 2;           // batch-pair group (8 batches)
    const int cg = og & 3;            // col group (4 cols)

    // x prefetch mapping: lane = batch (conflict-free STS), 4 d-quads / thread
    const int xb  = tid & 31;         // batch
    const int xdq = (tid >> 5) * 16;  // d4 base: 16 floats per thread (4 x float4)

    // prefetch x(0)
    float4 pf0, pf1, pf2, pf3;
    {
        const float* xr = X + (size_t)xb * TT * DD + 0 * DD + xdq;
        pf0 = __ldcg((const float4*)(xr +  0));
        pf1 = __ldcg((const float4*)(xr +  4));
        pf2 = __ldcg((const float4*)(xr +  8));
        pf3 = __ldcg((const float4*)(xr + 12));
    }

    for (int s = 0; s < TT; s++) {
        // ---- store prefetched x(s): lanes = consecutive b -> conflict-free ----
        {
            float* d0 = &hx[(HH + xdq) * 36 + xb];
            d0[0*36] = pf0.x; d0[1*36] = pf0.y; d0[ 2*36] = pf0.z; d0[ 3*36] = pf0.w;
            d0[4*36] = pf1.x; d0[5*36] = pf1.y; d0[ 6*36] = pf1.z; d0[ 7*36] = pf1.w;
            d0[8*36] = pf2.x; d0[9*36] = pf2.y; d0[10*36] = pf2.z; d0[11*36] = pf2.w;
            d0[12*36]= pf3.x; d0[13*36]= pf3.y; d0[14*36] = pf3.z; d0[15*36] = pf3.w;
        }
        __syncthreads();

        unsigned long long a00=0,a01=0,a02=0,a03=0, a10=0,a11=0,a12=0,a13=0,
                           a20=0,a21=0,a22=0,a23=0, a30=0,a31=0,a32=0,a33=0;

        // ---- x partial GEMM (h-independent) ----
        {
            const float* wp = Ws + (HH + kg * 8) * 16 + cg * 4;
            const float* hp = hx + (HH + kg * 8) * 36 + bg * 8;
#pragma unroll
            for (int kk = 0; kk < 8; kk++) { K_STEP(wp, hp); wp += 16; hp += 36; }
        }

        // ---- prefetch x(s+1); latency hides behind spin + h stage + h GEMM ----
        if (s + 1 < TT) {
            const float* xr = X + (size_t)xb * TT * DD + (size_t)(s + 1) * DD + xdq;
            pf0 = __ldcg((const float4*)(xr +  0));
            pf1 = __ldcg((const float4*)(xr +  4));
            pf2 = __ldcg((const float4*)(xr +  8));
            pf3 = __ldcg((const float4*)(xr + 12));
        }

        if (s > 0) {
            // ---- grid barrier: wait until all CTAs arrived s times this run ----
            if (tid == 0) {
                unsigned int target = base + (unsigned int)(NCTA * s);
                while ((int)(ldacq(&g_cnt) - target) < 0) { }
            }
            __syncthreads();

            // ---- stage h(s-1) (L2-direct) into hx rows [0..512) ----
            {
                const float* src = g_hT[s & 1];
                for (int i = tid; i < (HH * BB) / 4; i += NTHR) {
                    int k = i >> 3, b4 = (i & 7) << 2;
                    float4 v = __ldcg((const float4*)&src[k * BB + b4]);
                    *(float4*)&hx[k * 36 + b4] = v;
                }
            }
            __syncthreads();

            // ---- h GEMM ----
            {
                const float* wp = Ws + (kg * 16) * 16 + cg * 4;
                const float* hp = hx + (kg * 16) * 36 + bg * 8;
#pragma unroll
                for (int kk = 0; kk < 16; kk++) { K_STEP(wp, hp); wp += 16; hp += 36; }
            }
        }
        __syncthreads();   // hx h-row reads done before red (aliased) overwrites

        // ---- K-split partial store: red[kg][pair*16 + col] ----
        {
            int base2 = kg * 258 + (bg * 4) * 16 + cg * 4;   // float2 units, 16B aligned
            *(ulonglong2*)&red[base2         ] = make_ulonglong2(a00, a01);
            *(ulonglong2*)&red[base2      + 2] = make_ulonglong2(a02, a03);
            *(ulonglong2*)&red[base2 + 16    ] = make_ulonglong2(a10, a11);
            *(ulonglong2*)&red[base2 + 16 + 2] = make_ulonglong2(a12, a13);
            *(ulonglong2*)&red[base2 + 32    ] = make_ulonglong2(a20, a21);
            *(ulonglong2*)&red[base2 + 32 + 2] = make_ulonglong2(a22, a23);
            *(ulonglong2*)&red[base2 + 48    ] = make_ulonglong2(a30, a31);
            *(ulonglong2*)&red[base2 + 48 + 2] = make_ulonglong2(a32, a33);
        }
        __syncthreads();

        // ---- reduction over kg, split across all 512 threads (16 each) ----
        {
            int slot = tid & 255, half = tid >> 8;
            float2 acc = make_float2(0.0f, 0.0f);
#pragma unroll
            for (int g = 0; g < 16; g++) {
                float2 v = red[(half * 16 + g) * 258 + slot];
                acc.x += v.x; acc.y += v.y;
            }
            gb2[half * 256 + slot] = acc;
        }
        __syncthreads();

        // ---- gates / state update / publish ----
        if (tid < 128) {
            int b  = tid >> 2, u = tid & 3;
            int bp = b >> 1, hi = b & 1;
            int s0 = bp * 16 + u;
            float2 vi0 = gb2[s0     ], vi1 = gb2[256 + s0     ];
            float2 vf0 = gb2[s0 +  4], vf1 = gb2[256 + s0 +  4];
            float2 vg0 = gb2[s0 +  8], vg1 = gb2[256 + s0 +  8];
            float2 vo0 = gb2[s0 + 12], vo1 = gb2[256 + s0 + 12];
            float gi = (hi ? vi0.y + vi1.y : vi0.x + vi1.x) + bs[     u];
            float gf = (hi ? vf0.y + vf1.y : vf0.x + vf1.x) + bs[ 4 + u];
            float gg = (hi ? vg0.y + vg1.y : vg0.x + vg1.x) + bs[ 8 + u];
            float go = (hi ? vo0.y + vo1.y : vo0.x + vo1.x) + bs[12 + u];

            float c_old = cst[tid];
            float cn = sigf(gf) * c_old + sigf(gi) * tanhfast(gg);
            float hn = sigf(go) * tanhfast(cn);
            cst[tid] = cn;

            // publish h(s) to the buffer step s+1 reads
            g_hT[(s + 1) & 1][(hc + u) * BB + b] = hn;

            // ys output (unmasked, every step)
            out[2 * BB * HH + ((size_t)b * TT + s) * HH + hc + u] = hn;

            if (s < slen[b]) { lcs[tid] = cn; lhs[tid] = hn; }
        }
        __syncthreads();   // publishes ordered before tid0's release

        // ---- arrive: release-add on the monotone counter ----
        if (tid == 0) red_release_add(&g_cnt, 1u);
    }

    // ---- final latched carry ----
    if (tid < 128) {
        int b = tid >> 2, u = tid & 3;
        out[          (size_t)b * HH + hc + u] = lcs[tid];   // lc
        out[BB * HH + (size_t)b * HH + hc + u] = lhs[tid];   // lh
    }
}

extern "C" void kernel_launch(void* const* d_in, const int* in_sizes, int n_in,
                              void* d_out, int out_size) {
    const float* X    = (const float*)d_in[0];   // datamat [B,T,D]
    const int*   lens = (const int*)  d_in[1];   // datalens [B]
    const float* Wi   = (const float*)d_in[2];   // [D,4H]
    const float* Wh   = (const float*)d_in[3];   // [H,4H]
    const float* bias = (const float*)d_in[4];   // [4H]
    float* out = (float*)d_out;

    cudaFuncSetAttribute(k_lstm, cudaFuncAttributeMaxDynamicSharedMemorySize,
                         SMEM_BYTES);

    k_lstm<<<NCTA, NTHR, SMEM_BYTES>>>(X, lens, Wi, Wh, bias, out);
}